// round 4
// baseline (speedup 1.0000x reference)
#include <cuda_runtime.h>
#include <cuda_bf16.h>
#include <math.h>
#include <cstdint>

// Problem constants
#define B_  32
#define T_  4096
#define D_  1024
#define E_  128
#define K_  16
#define KEV_ 8
#define DK_ (D_ + E_)          // 1152
#define M_  (B_ * K_)          // 512 rows

// Output section offsets (float32, reference return order)
#define OFF_ENTRIES 0
#define OFF_VALID   (B_ * K_ * D_)                 // 524288
#define OFF_TIMES   (OFF_VALID + B_ * K_)          // 524800
#define OFF_HOLDER  (OFF_TIMES + B_ * K_)          // 525312
#define OUT_TOTAL   (OFF_HOLDER + B_ * K_ * E_)    // 590848

// Scratch: split-bf16 planes for A (gathered raw) and B (W)
__device__ int            g_chosen[M_];
__device__ int            g_valid[M_];
__device__ __nv_bfloat16  g_Ahi[(long)M_ * DK_];
__device__ __nv_bfloat16  g_Alo[(long)M_ * DK_];
__device__ __nv_bfloat16  g_Whi[(long)D_ * DK_];
__device__ __nv_bfloat16  g_Wlo[(long)D_ * DK_];

// ---------------------------------------------------------------------------
// helpers
// ---------------------------------------------------------------------------
__device__ __forceinline__ void split4(float4 v, uint2& hi, uint2& lo) {
    __nv_bfloat16 h0 = __float2bfloat16_rn(v.x);
    __nv_bfloat16 h1 = __float2bfloat16_rn(v.y);
    __nv_bfloat16 h2 = __float2bfloat16_rn(v.z);
    __nv_bfloat16 h3 = __float2bfloat16_rn(v.w);
    __nv_bfloat16 l0 = __float2bfloat16_rn(v.x - __bfloat162float(h0));
    __nv_bfloat16 l1 = __float2bfloat16_rn(v.y - __bfloat162float(h1));
    __nv_bfloat16 l2 = __float2bfloat16_rn(v.z - __bfloat162float(h2));
    __nv_bfloat16 l3 = __float2bfloat16_rn(v.w - __bfloat162float(h3));
    __nv_bfloat162 H01, H23, L01, L23;
    H01.x = h0; H01.y = h1; H23.x = h2; H23.y = h3;
    L01.x = l0; L01.y = l1; L23.x = l2; L23.y = l3;
    hi = make_uint2(*(uint32_t*)&H01, *(uint32_t*)&H23);
    lo = make_uint2(*(uint32_t*)&L01, *(uint32_t*)&L23);
}

__device__ __forceinline__ void mma_bf16(float* c, const uint32_t* a,
                                         const uint32_t* b) {
    asm volatile(
        "mma.sync.aligned.m16n8k16.row.col.f32.bf16.bf16.f32 "
        "{%0,%1,%2,%3}, {%4,%5,%6,%7}, {%8,%9}, {%0,%1,%2,%3};"
        : "+f"(c[0]), "+f"(c[1]), "+f"(c[2]), "+f"(c[3])
        : "r"(a[0]), "r"(a[1]), "r"(a[2]), "r"(a[3]),
          "r"(b[0]), "r"(b[1]));
}

__device__ __forceinline__ void ldmx4(uint32_t* r, uint32_t addr) {
    asm volatile(
        "ldmatrix.sync.aligned.m8n8.x4.shared.b16 {%0,%1,%2,%3}, [%4];"
        : "=r"(r[0]), "=r"(r[1]), "=r"(r[2]), "=r"(r[3]) : "r"(addr));
}

__device__ __forceinline__ void cp16(uint32_t smem_dst, const void* gsrc) {
    asm volatile("cp.async.cg.shared.global [%0], [%1], 16;"
                 :: "r"(smem_dst),
                    "l"((unsigned long long)__cvta_generic_to_global(gsrc)));
}
#define CP_COMMIT() asm volatile("cp.async.commit_group;")
#define CP_WAIT(n)  asm volatile("cp.async.wait_group %0;" :: "n"(n))

// ---------------------------------------------------------------------------
// Kernel 1 (fused): per-batch top-8 + merge with grid -> chosen; then
// warp-per-row gather + softmax + split-bf16 plane build + holder output.
// grid = 32 blocks x 256 threads.
// ---------------------------------------------------------------------------
__device__ __forceinline__ unsigned long long score_key(float v, int i) {
    unsigned u = __float_as_uint(v);
    u = (u & 0x80000000u) ? ~u : (u | 0x80000000u);
    return ((unsigned long long)u << 32) | (unsigned)(T_ - 1 - i);
}

__global__ void choose_build_kernel(const float* __restrict__ scores,
                                    const float* __restrict__ state,
                                    const float* __restrict__ hl,
                                    float* __restrict__ out, int out_size) {
    __shared__ unsigned long long wtop[8][KEV_];
    __shared__ int ev[KEV_];
    __shared__ int   sc[K_];
    __shared__ float sv[K_];

    const int b = blockIdx.x;
    const int tid = threadIdx.x;
    const int lane = tid & 31, warp = tid >> 5;
    const float* sb = scores + (long)b * T_;

    // ---- per-thread top-8 over 16 strided elements ----
    unsigned long long list[KEV_];
#pragma unroll
    for (int k = 0; k < KEV_; ++k) list[k] = 0ULL;
#pragma unroll
    for (int j = 0; j < T_ / 256; ++j) {
        int i = tid + j * 256;
        unsigned long long key = score_key(sb[i], i);
        if (key > list[KEV_ - 1]) {
            int p = KEV_ - 1;
            while (p > 0 && list[p - 1] < key) { list[p] = list[p - 1]; --p; }
            list[p] = key;
        }
    }
    int ptr = 0;
#pragma unroll
    for (int pick = 0; pick < KEV_; ++pick) {
        unsigned long long cand = (ptr < KEV_) ? list[ptr] : 0ULL;
        unsigned long long m = cand;
#pragma unroll
        for (int off = 16; off > 0; off >>= 1) {
            unsigned long long o = __shfl_xor_sync(0xffffffffu, m, off);
            if (o > m) m = o;
        }
        if (cand == m && cand != 0ULL) ++ptr;
        if (lane == 0) wtop[warp][pick] = m;
    }
    __syncthreads();
    if (warp == 0) {
        unsigned long long mylist[KEV_];
#pragma unroll
        for (int k = 0; k < KEV_; ++k)
            mylist[k] = (lane < 8) ? wtop[lane][k] : 0ULL;
        int p2 = 0;
#pragma unroll
        for (int pick = 0; pick < KEV_; ++pick) {
            unsigned long long cand = (lane < 8 && p2 < KEV_) ? mylist[p2] : 0ULL;
            unsigned long long m = cand;
#pragma unroll
            for (int off = 16; off > 0; off >>= 1) {
                unsigned long long o = __shfl_xor_sync(0xffffffffu, m, off);
                if (o > m) m = o;
            }
            if (cand == m && cand != 0ULL) ++p2;
            if (lane == 0) ev[pick] = (T_ - 1) - (int)(m & 0xFFFFFFFFu);
        }
    }
    __syncthreads();

    if (tid == 0) {
        int c[KEV_ + K_];
        for (int i = 0; i < KEV_; ++i) c[i] = ev[i];
        float step = (float)(T_ - 1) / (float)(K_ - 1);
        for (int i = 0; i < K_; ++i) c[KEV_ + i] = (int)((float)i * step);
        for (int i = 1; i < KEV_ + K_; ++i) {
            int v = c[i], j = i - 1;
            while (j >= 0 && c[j] > v) { c[j + 1] = c[j]; --j; }
            c[j + 1] = v;
        }
        int u[KEV_ + K_]; int n = 0;
        for (int i = 0; i < KEV_ + K_; ++i)
            if (i == 0 || c[i] != c[i - 1]) u[n++] = c[i];
        int nv = n < K_ ? n : K_;
        for (int k = 0; k < K_; ++k) {
            int ch = (k < n) ? u[k] : 0;
            int vd = (k < nv) ? 1 : 0;
            sc[k] = ch; sv[k] = (float)vd;
            g_chosen[b * K_ + k] = ch;
            g_valid[b * K_ + k]  = vd;
            if (out_size >= OUT_TOTAL) {
                out[OFF_VALID + b * K_ + k] = (float)vd;
                out[OFF_TIMES + b * K_ + k] = (float)(ch * vd);
            }
        }
    }
    __syncthreads();

    // ---- warp-per-row: gather + softmax + split planes + holder ----
#pragma unroll
    for (int rr = warp; rr < K_; rr += 8) {
        const int row = b * K_ + rr;
        const int idx = sc[rr];
        const float vf = sv[rr];

        // holder logits: 128 floats = 32 lanes x float4
        const float4 hv =
            ((const float4*)(hl + ((long)b * T_ + idx) * E_))[lane];
        if (out_size >= OUT_TOTAL) {
            float4 ho;
            ho.x = hv.x * vf; ho.y = hv.y * vf;
            ho.z = hv.z * vf; ho.w = hv.w * vf;
            ((float4*)(out + OFF_HOLDER + (long)row * E_))[lane] = ho;
        }
        // softmax
        float mx = fmaxf(fmaxf(hv.x, hv.y), fmaxf(hv.z, hv.w));
#pragma unroll
        for (int off = 16; off > 0; off >>= 1)
            mx = fmaxf(mx, __shfl_xor_sync(0xffffffffu, mx, off));
        float4 ex;
        ex.x = expf(hv.x - mx); ex.y = expf(hv.y - mx);
        ex.z = expf(hv.z - mx); ex.w = expf(hv.w - mx);
        float s = ex.x + ex.y + ex.z + ex.w;
#pragma unroll
        for (int off = 16; off > 0; off >>= 1)
            s += __shfl_xor_sync(0xffffffffu, s, off);
        float inv = 1.0f / s;
        float4 p;
        p.x = ex.x * inv; p.y = ex.y * inv; p.z = ex.z * inv; p.w = ex.w * inv;

        __nv_bfloat16* hi = g_Ahi + (long)row * DK_;
        __nv_bfloat16* lo = g_Alo + (long)row * DK_;
        uint2 h2, l2;
        split4(p, h2, l2);
        *(uint2*)(hi + D_ + lane * 4) = h2;
        *(uint2*)(lo + D_ + lane * 4) = l2;

        // state row: 1024 floats = 256 float4; lane handles 8
        const float4* src = (const float4*)(state + ((long)b * T_ + idx) * D_);
#pragma unroll
        for (int t = 0; t < 8; ++t) {
            int q = lane + t * 32;
            split4(src[q], h2, l2);
            *(uint2*)(hi + q * 4) = h2;
            *(uint2*)(lo + q * 4) = l2;
        }
    }
}

// ---------------------------------------------------------------------------
// Kernel 2: pack W -> split bf16 planes
// ---------------------------------------------------------------------------
__global__ void pack_w_kernel(const float* __restrict__ W) {
    long i = (long)blockIdx.x * 256 + threadIdx.x;   // float4 index
    float4 v = ((const float4*)W)[i];
    uint2 hi, lo;
    split4(v, hi, lo);
    *(uint2*)(g_Whi + i * 4) = hi;
    *(uint2*)(g_Wlo + i * 4) = lo;
}

// ---------------------------------------------------------------------------
// Kernel 3: HMMA split-bf16 GEMM, ldmatrix + 4-stage cp.async pipeline.
// BM=BN=64, BK=32, 256 threads (8 warps 2x4), warp tile 32x16,
// per warp 2x2 m16n8 tiles, 3 accumulation passes (hh, hl, lh).
// ---------------------------------------------------------------------------
#define GBM 64
#define GBN 64
#define GBK 32
#define NSTAGE (DK_ / GBK)    // 36
#define STAGES 4
#define PADK 40               // k stride (bf16) per smem row; 80B, conflict-free
#define PLANE_ELEMS (64 * PADK)           // 2560 elems = 5120 B
#define STAGE_ELEMS (4 * PLANE_ELEMS)     // 4 planes
#define SMEM_BYTES (STAGES * STAGE_ELEMS * 2)   // 81920

__global__ __launch_bounds__(256)
void gemm_hmma_kernel(const float* __restrict__ bias,
                      const float* __restrict__ time_table,
                      float* __restrict__ out) {
    extern __shared__ __nv_bfloat16 smem[];   // [STAGES][4][PLANE_ELEMS]
    const uint32_t sbase = (uint32_t)__cvta_generic_to_shared(smem);

    const int tid = threadIdx.x;
    const int lane = tid & 31;
    const int warp = tid >> 5;             // 0..7
    const int warp_m = (warp & 1) * 32;    // 0 or 32
    const int warp_n = (warp >> 1) * 16;   // 0,16,32,48
    const int bm = blockIdx.y * GBM;
    const int bn = blockIdx.x * GBN;

    // cp.async mapping: lrow 0..63, lcq 0..3 (16B chunks of 64B row)
    const int lrow = tid >> 2;
    const int lcq  = tid & 3;

    auto load_stage = [&](int st, int buf) {
        const long k0 = (long)st * GBK;
        const long aoff = (long)(bm + lrow) * DK_ + k0 + lcq * 8;
        const long boff = (long)(bn + lrow) * DK_ + k0 + lcq * 8;
        const uint32_t soff = (uint32_t)(lrow * PADK + lcq * 8);
        const uint32_t sb0 = sbase + (uint32_t)(buf * STAGE_ELEMS) * 2;
        cp16(sb0 + (0 * PLANE_ELEMS + soff) * 2, g_Ahi + aoff);
        cp16(sb0 + (1 * PLANE_ELEMS + soff) * 2, g_Alo + aoff);
        cp16(sb0 + (2 * PLANE_ELEMS + soff) * 2, g_Whi + boff);
        cp16(sb0 + (3 * PLANE_ELEMS + soff) * 2, g_Wlo + boff);
        CP_COMMIT();
    };

    // ldmatrix per-lane offsets: quad 0..3 -> (m_off, k_off)
    const int r8 = lane & 7;
    const int quad = lane >> 3;
    const int lm = (quad & 1) * 8 + r8;
    const int lk = (quad >> 1) * 8;

    float acc[2][2][4];
#pragma unroll
    for (int i = 0; i < 2; ++i)
#pragma unroll
        for (int j = 0; j < 2; ++j)
#pragma unroll
            for (int q = 0; q < 4; ++q) acc[i][j][q] = 0.f;

    load_stage(0, 0);
    load_stage(1, 1);
    load_stage(2, 2);

    for (int st = 0; st < NSTAGE; ++st) {
        if (st < NSTAGE - 2)       { CP_WAIT(2); }
        else if (st == NSTAGE - 2) { CP_WAIT(1); }
        else                       { CP_WAIT(0); }
        __syncthreads();
        if (st + 3 < NSTAGE) load_stage(st + 3, (st + 3) & 3);

        const uint32_t sb0 = sbase + (uint32_t)((st & 3) * STAGE_ELEMS) * 2;
#pragma unroll
        for (int ks = 0; ks < 2; ++ks) {
            const int kb = ks * 16;
            uint32_t ahi[2][4], alo[2][4], bh[4], bl[4];
#pragma unroll
            for (int mt = 0; mt < 2; ++mt) {
                uint32_t ra = (uint32_t)((warp_m + mt * 16 + lm) * PADK + kb + lk) * 2;
                ldmx4(ahi[mt], sb0 + (0 * PLANE_ELEMS) * 2 + ra);
                ldmx4(alo[mt], sb0 + (1 * PLANE_ELEMS) * 2 + ra);
            }
            {
                uint32_t rb = (uint32_t)((warp_n + lm) * PADK + kb + lk) * 2;
                ldmx4(bh, sb0 + (2 * PLANE_ELEMS) * 2 + rb);
                ldmx4(bl, sb0 + (3 * PLANE_ELEMS) * 2 + rb);
            }
            // B fragments: nt0 = {r0, r2}, nt1 = {r1, r3}
            uint32_t bhi0[2] = {bh[0], bh[2]}, bhi1[2] = {bh[1], bh[3]};
            uint32_t blo0[2] = {bl[0], bl[2]}, blo1[2] = {bl[1], bl[3]};

            // pass hh
            mma_bf16(acc[0][0], ahi[0], bhi0);
            mma_bf16(acc[0][1], ahi[0], bhi1);
            mma_bf16(acc[1][0], ahi[1], bhi0);
            mma_bf16(acc[1][1], ahi[1], bhi1);
            // pass hl
            mma_bf16(acc[0][0], ahi[0], blo0);
            mma_bf16(acc[0][1], ahi[0], blo1);
            mma_bf16(acc[1][0], ahi[1], blo0);
            mma_bf16(acc[1][1], ahi[1], blo1);
            // pass lh
            mma_bf16(acc[0][0], alo[0], bhi0);
            mma_bf16(acc[0][1], alo[0], bhi1);
            mma_bf16(acc[1][0], alo[1], bhi0);
            mma_bf16(acc[1][1], alo[1], bhi1);
        }
    }

    // ---- epilogue ----
    const int r = lane >> 2;
    const int kq = (lane & 3) * 2;
#pragma unroll
    for (int mt = 0; mt < 2; ++mt) {
#pragma unroll
        for (int half = 0; half < 2; ++half) {
            const int m = bm + warp_m + mt * 16 + r + half * 8;
            int tt = g_chosen[m];
            tt = tt < 0 ? 0 : (tt > 511 ? 511 : tt);
            const float vf = (float)g_valid[m];
            const float* te = time_table + (long)tt * D_;
            float* op = out + OFF_ENTRIES + (long)m * D_;
#pragma unroll
            for (int nt = 0; nt < 2; ++nt) {
                const int n0 = bn + warp_n + nt * 8 + kq;
                const float c0 = acc[mt][nt][half * 2 + 0];
                const float c1 = acc[mt][nt][half * 2 + 1];
                float2 o;
                o.x = (c0 + bias[n0]     + te[n0])     * vf;
                o.y = (c1 + bias[n0 + 1] + te[n0 + 1]) * vf;
                *(float2*)(op + n0) = o;
            }
        }
    }
}

// ---------------------------------------------------------------------------
// Launch. Inputs: state_seq, holder_logits, event_scores, W, b, time_table
// ---------------------------------------------------------------------------
extern "C" void kernel_launch(void* const* d_in, const int* in_sizes, int n_in,
                              void* d_out, int out_size) {
    const float* state  = (const float*)d_in[0];
    const float* hl     = (const float*)d_in[1];
    const float* scores = (const float*)d_in[2];
    const float* W      = (const float*)d_in[3];
    const float* bias   = (const float*)d_in[4];
    const float* ttab   = (const float*)d_in[5];
    float* out = (float*)d_out;

    cudaFuncSetAttribute(gemm_hmma_kernel,
                         cudaFuncAttributeMaxDynamicSharedMemorySize,
                         SMEM_BYTES);

    choose_build_kernel<<<B_, 256>>>(scores, state, hl, out, out_size);
    pack_w_kernel<<<(D_ * DK_ / 4) / 256, 256>>>(W);
    dim3 grid(D_ / GBN, M_ / GBM);   // (16, 8) = 128 CTAs
    gemm_hmma_kernel<<<grid, 256, SMEM_BYTES>>>(bias, ttab, out);
}

// round 5
// speedup vs baseline: 1.0655x; 1.0655x over previous
#include <cuda_runtime.h>
#include <cuda_bf16.h>
#include <math.h>
#include <cstdint>

// Problem constants
#define B_  32
#define T_  4096
#define D_  1024
#define E_  128
#define K_  16
#define KEV_ 8
#define DK_ (D_ + E_)          // 1152
#define M_  (B_ * K_)          // 512 rows

// Output section offsets (float32, reference return order)
#define OFF_ENTRIES 0
#define OFF_VALID   (B_ * K_ * D_)                 // 524288
#define OFF_TIMES   (OFF_VALID + B_ * K_)          // 524800
#define OFF_HOLDER  (OFF_TIMES + B_ * K_)          // 525312
#define OUT_TOTAL   (OFF_HOLDER + B_ * K_ * E_)    // 590848

// Scratch: split-bf16 planes for A (gathered raw) and B (W)
__device__ int            g_chosen[M_];
__device__ int            g_valid[M_];
__device__ __nv_bfloat16  g_Ahi[(long)M_ * DK_];
__device__ __nv_bfloat16  g_Alo[(long)M_ * DK_];
__device__ __nv_bfloat16  g_Whi[(long)D_ * DK_];
__device__ __nv_bfloat16  g_Wlo[(long)D_ * DK_];

// ---------------------------------------------------------------------------
// helpers
// ---------------------------------------------------------------------------
__device__ __forceinline__ void split4(float4 v, uint2& hi, uint2& lo) {
    __nv_bfloat16 h0 = __float2bfloat16_rn(v.x);
    __nv_bfloat16 h1 = __float2bfloat16_rn(v.y);
    __nv_bfloat16 h2 = __float2bfloat16_rn(v.z);
    __nv_bfloat16 h3 = __float2bfloat16_rn(v.w);
    __nv_bfloat16 l0 = __float2bfloat16_rn(v.x - __bfloat162float(h0));
    __nv_bfloat16 l1 = __float2bfloat16_rn(v.y - __bfloat162float(h1));
    __nv_bfloat16 l2 = __float2bfloat16_rn(v.z - __bfloat162float(h2));
    __nv_bfloat16 l3 = __float2bfloat16_rn(v.w - __bfloat162float(h3));
    __nv_bfloat162 H01, H23, L01, L23;
    H01.x = h0; H01.y = h1; H23.x = h2; H23.y = h3;
    L01.x = l0; L01.y = l1; L23.x = l2; L23.y = l3;
    hi = make_uint2(*(uint32_t*)&H01, *(uint32_t*)&H23);
    lo = make_uint2(*(uint32_t*)&L01, *(uint32_t*)&L23);
}

__device__ __forceinline__ void mma_bf16(float* c, const uint32_t* a,
                                         const uint32_t* b) {
    asm volatile(
        "mma.sync.aligned.m16n8k16.row.col.f32.bf16.bf16.f32 "
        "{%0,%1,%2,%3}, {%4,%5,%6,%7}, {%8,%9}, {%0,%1,%2,%3};"
        : "+f"(c[0]), "+f"(c[1]), "+f"(c[2]), "+f"(c[3])
        : "r"(a[0]), "r"(a[1]), "r"(a[2]), "r"(a[3]),
          "r"(b[0]), "r"(b[1]));
}

__device__ __forceinline__ void ldmx4(uint32_t* r, uint32_t addr) {
    asm volatile(
        "ldmatrix.sync.aligned.m8n8.x4.shared.b16 {%0,%1,%2,%3}, [%4];"
        : "=r"(r[0]), "=r"(r[1]), "=r"(r[2]), "=r"(r[3]) : "r"(addr));
}

__device__ __forceinline__ void cp16(uint32_t smem_dst, const void* gsrc) {
    asm volatile("cp.async.cg.shared.global [%0], [%1], 16;"
                 :: "r"(smem_dst),
                    "l"((unsigned long long)__cvta_generic_to_global(gsrc)));
}
#define CP_COMMIT() asm volatile("cp.async.commit_group;")
#define CP_WAIT(n)  asm volatile("cp.async.wait_group %0;" :: "n"(n))

// ---------------------------------------------------------------------------
// Kernel 1 (fused): per-batch top-8 (register-only, no dynamic indexing)
// + merge with uniform grid; then warp-per-row gather/softmax/split planes.
// grid = 32 blocks x 512 threads (16 warps = 16 checkpoint rows).
// ---------------------------------------------------------------------------
__device__ __forceinline__ unsigned long long score_key(float v, int i) {
    unsigned u = __float_as_uint(v);
    u = (u & 0x80000000u) ? ~u : (u | 0x80000000u);
    return ((unsigned long long)u << 32) | (unsigned)(T_ - 1 - i);
}

__global__ __launch_bounds__(512)
void choose_build_kernel(const float* __restrict__ scores,
                         const float* __restrict__ state,
                         const float* __restrict__ hl,
                         float* __restrict__ out, int out_size) {
    __shared__ unsigned long long wmax[16];
    __shared__ int ev[KEV_];
    __shared__ int   sc[K_];
    __shared__ float sv[K_];

    const int b = blockIdx.x;
    const int tid = threadIdx.x;          // 0..511
    const int lane = tid & 31, warp = tid >> 5;   // 16 warps
    const float* sb = scores + (long)b * T_;

    // ---- load 8 keys per thread, all statically indexed ----
    unsigned long long v[8];
#pragma unroll
    for (int j = 0; j < 8; ++j)
        v[j] = score_key(sb[tid + j * 512], tid + j * 512);

    // ---- 8 rounds of block-wide argmax ----
#pragma unroll
    for (int round = 0; round < KEV_; ++round) {
        unsigned long long m = v[0];
#pragma unroll
        for (int j = 1; j < 8; ++j) m = (v[j] > m) ? v[j] : m;
#pragma unroll
        for (int off = 16; off > 0; off >>= 1) {
            unsigned long long o = __shfl_xor_sync(0xffffffffu, m, off);
            m = (o > m) ? o : m;
        }
        if (lane == 0) wmax[warp] = m;
        __syncthreads();
        unsigned long long bm = wmax[0];
#pragma unroll
        for (int j = 1; j < 16; ++j) bm = (wmax[j] > bm) ? wmax[j] : bm;
        // clear winner (keys unique)
#pragma unroll
        for (int j = 0; j < 8; ++j) if (v[j] == bm) v[j] = 0ULL;
        if (tid == 0) ev[round] = (T_ - 1) - (int)(bm & 0xFFFFFFFFu);
        __syncthreads();
    }

    // ---- merge + sort + unique (tiny, single thread) ----
    if (tid == 0) {
        int c[KEV_ + K_];
#pragma unroll
        for (int i = 0; i < KEV_; ++i) c[i] = ev[i];
        float step = (float)(T_ - 1) / (float)(K_ - 1);
#pragma unroll
        for (int i = 0; i < K_; ++i) c[KEV_ + i] = (int)((float)i * step);
        for (int i = 1; i < KEV_ + K_; ++i) {
            int vv = c[i], j = i - 1;
            while (j >= 0 && c[j] > vv) { c[j + 1] = c[j]; --j; }
            c[j + 1] = vv;
        }
        int u[KEV_ + K_]; int n = 0;
        for (int i = 0; i < KEV_ + K_; ++i)
            if (i == 0 || c[i] != c[i - 1]) u[n++] = c[i];
        int nv = n < K_ ? n : K_;
        for (int k = 0; k < K_; ++k) {
            int ch = (k < n) ? u[k] : 0;
            int vd = (k < nv) ? 1 : 0;
            sc[k] = ch; sv[k] = (float)vd;
            g_chosen[b * K_ + k] = ch;
            g_valid[b * K_ + k]  = vd;
            if (out_size >= OUT_TOTAL) {
                out[OFF_VALID + b * K_ + k] = (float)vd;
                out[OFF_TIMES + b * K_ + k] = (float)(ch * vd);
            }
        }
    }
    __syncthreads();

    // ---- warp-per-row: gather + softmax + split planes + holder ----
    {
        const int rr = warp;               // exactly 16 rows
        const int row = b * K_ + rr;
        const int idx = sc[rr];
        const float vf = sv[rr];

        const float4 hv =
            ((const float4*)(hl + ((long)b * T_ + idx) * E_))[lane];
        if (out_size >= OUT_TOTAL) {
            float4 ho;
            ho.x = hv.x * vf; ho.y = hv.y * vf;
            ho.z = hv.z * vf; ho.w = hv.w * vf;
            ((float4*)(out + OFF_HOLDER + (long)row * E_))[lane] = ho;
        }
        float mx = fmaxf(fmaxf(hv.x, hv.y), fmaxf(hv.z, hv.w));
#pragma unroll
        for (int off = 16; off > 0; off >>= 1)
            mx = fmaxf(mx, __shfl_xor_sync(0xffffffffu, mx, off));
        float4 ex;
        ex.x = expf(hv.x - mx); ex.y = expf(hv.y - mx);
        ex.z = expf(hv.z - mx); ex.w = expf(hv.w - mx);
        float s = ex.x + ex.y + ex.z + ex.w;
#pragma unroll
        for (int off = 16; off > 0; off >>= 1)
            s += __shfl_xor_sync(0xffffffffu, s, off);
        float inv = 1.0f / s;
        float4 p;
        p.x = ex.x * inv; p.y = ex.y * inv; p.z = ex.z * inv; p.w = ex.w * inv;

        __nv_bfloat16* hi = g_Ahi + (long)row * DK_;
        __nv_bfloat16* lo = g_Alo + (long)row * DK_;
        uint2 h2, l2;
        split4(p, h2, l2);
        *(uint2*)(hi + D_ + lane * 4) = h2;
        *(uint2*)(lo + D_ + lane * 4) = l2;

        const float4* src = (const float4*)(state + ((long)b * T_ + idx) * D_);
#pragma unroll
        for (int t = 0; t < 8; ++t) {
            int q = lane + t * 32;
            split4(src[q], h2, l2);
            *(uint2*)(hi + q * 4) = h2;
            *(uint2*)(lo + q * 4) = l2;
        }
    }
}

// ---------------------------------------------------------------------------
// Kernel 2: pack W -> split bf16 planes
// ---------------------------------------------------------------------------
__global__ void pack_w_kernel(const float* __restrict__ W) {
    long i = (long)blockIdx.x * 256 + threadIdx.x;   // float4 index
    float4 v = ((const float4*)W)[i];
    uint2 hi, lo;
    split4(v, hi, lo);
    *(uint2*)(g_Whi + i * 4) = hi;
    *(uint2*)(g_Wlo + i * 4) = lo;
}

// ---------------------------------------------------------------------------
// Kernel 3: HMMA split-bf16 GEMM, ldmatrix + 4-stage cp.async pipeline.
// (unchanged from R4 — measured ~17us; next target after selection fix)
// ---------------------------------------------------------------------------
#define GBM 64
#define GBN 64
#define GBK 32
#define NSTAGE (DK_ / GBK)    // 36
#define STAGES 4
#define PADK 40               // k stride (bf16) per smem row; 80B, conflict-free
#define PLANE_ELEMS (64 * PADK)           // 2560 elems = 5120 B
#define STAGE_ELEMS (4 * PLANE_ELEMS)     // 4 planes
#define SMEM_BYTES (STAGES * STAGE_ELEMS * 2)   // 81920

__global__ __launch_bounds__(256)
void gemm_hmma_kernel(const float* __restrict__ bias,
                      const float* __restrict__ time_table,
                      float* __restrict__ out) {
    extern __shared__ __nv_bfloat16 smem[];   // [STAGES][4][PLANE_ELEMS]
    const uint32_t sbase = (uint32_t)__cvta_generic_to_shared(smem);

    const int tid = threadIdx.x;
    const int lane = tid & 31;
    const int warp = tid >> 5;             // 0..7
    const int warp_m = (warp & 1) * 32;    // 0 or 32
    const int warp_n = (warp >> 1) * 16;   // 0,16,32,48
    const int bm = blockIdx.y * GBM;
    const int bn = blockIdx.x * GBN;

    const int lrow = tid >> 2;
    const int lcq  = tid & 3;

    auto load_stage = [&](int st, int buf) {
        const long k0 = (long)st * GBK;
        const long aoff = (long)(bm + lrow) * DK_ + k0 + lcq * 8;
        const long boff = (long)(bn + lrow) * DK_ + k0 + lcq * 8;
        const uint32_t soff = (uint32_t)(lrow * PADK + lcq * 8);
        const uint32_t sb0 = sbase + (uint32_t)(buf * STAGE_ELEMS) * 2;
        cp16(sb0 + (0 * PLANE_ELEMS + soff) * 2, g_Ahi + aoff);
        cp16(sb0 + (1 * PLANE_ELEMS + soff) * 2, g_Alo + aoff);
        cp16(sb0 + (2 * PLANE_ELEMS + soff) * 2, g_Whi + boff);
        cp16(sb0 + (3 * PLANE_ELEMS + soff) * 2, g_Wlo + boff);
        CP_COMMIT();
    };

    const int r8 = lane & 7;
    const int quad = lane >> 3;
    const int lm = (quad & 1) * 8 + r8;
    const int lk = (quad >> 1) * 8;

    float acc[2][2][4];
#pragma unroll
    for (int i = 0; i < 2; ++i)
#pragma unroll
        for (int j = 0; j < 2; ++j)
#pragma unroll
            for (int q = 0; q < 4; ++q) acc[i][j][q] = 0.f;

    load_stage(0, 0);
    load_stage(1, 1);
    load_stage(2, 2);

    for (int st = 0; st < NSTAGE; ++st) {
        if (st < NSTAGE - 2)       { CP_WAIT(2); }
        else if (st == NSTAGE - 2) { CP_WAIT(1); }
        else                       { CP_WAIT(0); }
        __syncthreads();
        if (st + 3 < NSTAGE) load_stage(st + 3, (st + 3) & 3);

        const uint32_t sb0 = sbase + (uint32_t)((st & 3) * STAGE_ELEMS) * 2;
#pragma unroll
        for (int ks = 0; ks < 2; ++ks) {
            const int kb = ks * 16;
            uint32_t ahi[2][4], alo[2][4], bh[4], bl[4];
#pragma unroll
            for (int mt = 0; mt < 2; ++mt) {
                uint32_t ra = (uint32_t)((warp_m + mt * 16 + lm) * PADK + kb + lk) * 2;
                ldmx4(ahi[mt], sb0 + (0 * PLANE_ELEMS) * 2 + ra);
                ldmx4(alo[mt], sb0 + (1 * PLANE_ELEMS) * 2 + ra);
            }
            {
                uint32_t rb = (uint32_t)((warp_n + lm) * PADK + kb + lk) * 2;
                ldmx4(bh, sb0 + (2 * PLANE_ELEMS) * 2 + rb);
                ldmx4(bl, sb0 + (3 * PLANE_ELEMS) * 2 + rb);
            }
            uint32_t bhi0[2] = {bh[0], bh[2]}, bhi1[2] = {bh[1], bh[3]};
            uint32_t blo0[2] = {bl[0], bl[2]}, blo1[2] = {bl[1], bl[3]};

            mma_bf16(acc[0][0], ahi[0], bhi0);
            mma_bf16(acc[0][1], ahi[0], bhi1);
            mma_bf16(acc[1][0], ahi[1], bhi0);
            mma_bf16(acc[1][1], ahi[1], bhi1);
            mma_bf16(acc[0][0], ahi[0], blo0);
            mma_bf16(acc[0][1], ahi[0], blo1);
            mma_bf16(acc[1][0], ahi[1], blo0);
            mma_bf16(acc[1][1], ahi[1], blo1);
            mma_bf16(acc[0][0], alo[0], bhi0);
            mma_bf16(acc[0][1], alo[0], bhi1);
            mma_bf16(acc[1][0], alo[1], bhi0);
            mma_bf16(acc[1][1], alo[1], bhi1);
        }
    }

    // ---- epilogue ----
    const int r = lane >> 2;
    const int kq = (lane & 3) * 2;
#pragma unroll
    for (int mt = 0; mt < 2; ++mt) {
#pragma unroll
        for (int half = 0; half < 2; ++half) {
            const int m = bm + warp_m + mt * 16 + r + half * 8;
            int tt = g_chosen[m];
            tt = tt < 0 ? 0 : (tt > 511 ? 511 : tt);
            const float vf = (float)g_valid[m];
            const float* te = time_table + (long)tt * D_;
            float* op = out + OFF_ENTRIES + (long)m * D_;
#pragma unroll
            for (int nt = 0; nt < 2; ++nt) {
                const int n0 = bn + warp_n + nt * 8 + kq;
                const float c0 = acc[mt][nt][half * 2 + 0];
                const float c1 = acc[mt][nt][half * 2 + 1];
                float2 o;
                o.x = (c0 + bias[n0]     + te[n0])     * vf;
                o.y = (c1 + bias[n0 + 1] + te[n0 + 1]) * vf;
                *(float2*)(op + n0) = o;
            }
        }
    }
}

// ---------------------------------------------------------------------------
// Launch. Inputs: state_seq, holder_logits, event_scores, W, b, time_table
// ---------------------------------------------------------------------------
extern "C" void kernel_launch(void* const* d_in, const int* in_sizes, int n_in,
                              void* d_out, int out_size) {
    const float* state  = (const float*)d_in[0];
    const float* hl     = (const float*)d_in[1];
    const float* scores = (const float*)d_in[2];
    const float* W      = (const float*)d_in[3];
    const float* bias   = (const float*)d_in[4];
    const float* ttab   = (const float*)d_in[5];
    float* out = (float*)d_out;

    cudaFuncSetAttribute(gemm_hmma_kernel,
                         cudaFuncAttributeMaxDynamicSharedMemorySize,
                         SMEM_BYTES);

    pack_w_kernel<<<(D_ * DK_ / 4) / 256, 256>>>(W);
    choose_build_kernel<<<B_, 512>>>(scores, state, hl, out, out_size);
    dim3 grid(D_ / GBN, M_ / GBM);   // (16, 8) = 128 CTAs
    gemm_hmma_kernel<<<grid, 256, SMEM_BYTES>>>(bias, ttab, out);
}

// round 6
// speedup vs baseline: 1.2878x; 1.2086x over previous
#include <cuda_runtime.h>
#include <cuda_bf16.h>
#include <math.h>
#include <cstdint>

// Problem constants
#define B_  32
#define T_  4096
#define D_  1024
#define E_  128
#define K_  16
#define KEV_ 8
#define DK_ (D_ + E_)          // 1152
#define M_  (B_ * K_)          // 512 rows

// Output section offsets (float32, reference return order)
#define OFF_ENTRIES 0
#define OFF_VALID   (B_ * K_ * D_)                 // 524288
#define OFF_TIMES   (OFF_VALID + B_ * K_)          // 524800
#define OFF_HOLDER  (OFF_TIMES + B_ * K_)          // 525312
#define OUT_TOTAL   (OFF_HOLDER + B_ * K_ * E_)    // 590848

// Scratch: split-bf16 planes for A (gathered raw) and B (W)
__device__ int            g_chosen[M_];
__device__ int            g_valid[M_];
__device__ __nv_bfloat16  g_Ahi[(long)M_ * DK_];
__device__ __nv_bfloat16  g_Alo[(long)M_ * DK_];
__device__ __nv_bfloat16  g_Whi[(long)D_ * DK_];
__device__ __nv_bfloat16  g_Wlo[(long)D_ * DK_];

// ---------------------------------------------------------------------------
// helpers
// ---------------------------------------------------------------------------
__device__ __forceinline__ void split4(float4 v, uint2& hi, uint2& lo) {
    __nv_bfloat16 h0 = __float2bfloat16_rn(v.x);
    __nv_bfloat16 h1 = __float2bfloat16_rn(v.y);
    __nv_bfloat16 h2 = __float2bfloat16_rn(v.z);
    __nv_bfloat16 h3 = __float2bfloat16_rn(v.w);
    __nv_bfloat16 l0 = __float2bfloat16_rn(v.x - __bfloat162float(h0));
    __nv_bfloat16 l1 = __float2bfloat16_rn(v.y - __bfloat162float(h1));
    __nv_bfloat16 l2 = __float2bfloat16_rn(v.z - __bfloat162float(h2));
    __nv_bfloat16 l3 = __float2bfloat16_rn(v.w - __bfloat162float(h3));
    __nv_bfloat162 H01, H23, L01, L23;
    H01.x = h0; H01.y = h1; H23.x = h2; H23.y = h3;
    L01.x = l0; L01.y = l1; L23.x = l2; L23.y = l3;
    hi = make_uint2(*(uint32_t*)&H01, *(uint32_t*)&H23);
    lo = make_uint2(*(uint32_t*)&L01, *(uint32_t*)&L23);
}

__device__ __forceinline__ void mma_bf16(float* c, const uint32_t* a,
                                         const uint32_t* b) {
    asm volatile(
        "mma.sync.aligned.m16n8k16.row.col.f32.bf16.bf16.f32 "
        "{%0,%1,%2,%3}, {%4,%5,%6,%7}, {%8,%9}, {%0,%1,%2,%3};"
        : "+f"(c[0]), "+f"(c[1]), "+f"(c[2]), "+f"(c[3])
        : "r"(a[0]), "r"(a[1]), "r"(a[2]), "r"(a[3]),
          "r"(b[0]), "r"(b[1]));
}

__device__ __forceinline__ void ldmx4(uint32_t* r, uint32_t addr) {
    asm volatile(
        "ldmatrix.sync.aligned.m8n8.x4.shared.b16 {%0,%1,%2,%3}, [%4];"
        : "=r"(r[0]), "=r"(r[1]), "=r"(r[2]), "=r"(r[3]) : "r"(addr));
}

__device__ __forceinline__ void cp16(uint32_t smem_dst, const void* gsrc) {
    asm volatile("cp.async.cg.shared.global [%0], [%1], 16;"
                 :: "r"(smem_dst),
                    "l"((unsigned long long)__cvta_generic_to_global(gsrc)));
}
#define CP_COMMIT() asm volatile("cp.async.commit_group;")
#define CP_WAIT(n)  asm volatile("cp.async.wait_group %0;" :: "n"(n))

__device__ __forceinline__ unsigned long long score_key(float v, int i) {
    unsigned u = __float_as_uint(v);
    u = (u & 0x80000000u) ? ~u : (u | 0x80000000u);
    return ((unsigned long long)u << 32) | (unsigned)(T_ - 1 - i);
}

// ---------------------------------------------------------------------------
// Kernel 1 (prep, heterogeneous grid):
//   blocks [0,32): per-batch top-8 (registers) + parallel warp dedup/merge
//                  + warp-per-row gather/softmax/split-plane build
//   blocks [32,608): pack W -> split bf16 planes (576 blocks x 512 float4)
// ---------------------------------------------------------------------------
#define PACK_BLOCKS ((D_ * DK_ / 4) / 512)   // 576
#define PREP_GRID   (B_ + PACK_BLOCKS)       // 608

__global__ __launch_bounds__(512)
void prep_kernel(const float* __restrict__ scores,
                 const float* __restrict__ state,
                 const float* __restrict__ hl,
                 const float* __restrict__ W,
                 float* __restrict__ out, int out_size) {
    // ---------------- W packing blocks ----------------
    if (blockIdx.x >= B_) {
        long i = (long)(blockIdx.x - B_) * 512 + threadIdx.x;  // float4 idx
        float4 v = ((const float4*)W)[i];
        uint2 hi, lo;
        split4(v, hi, lo);
        *(uint2*)(g_Whi + i * 4) = hi;
        *(uint2*)(g_Wlo + i * 4) = lo;
        return;
    }

    // ---------------- choose + build blocks ----------------
    __shared__ unsigned long long wmax[16];
    __shared__ int ev[KEV_];
    __shared__ int   sc[K_];
    __shared__ float sv[K_];

    const int b = blockIdx.x;
    const int tid = threadIdx.x;          // 0..511
    const int lane = tid & 31, warp = tid >> 5;   // 16 warps
    const float* sb = scores + (long)b * T_;

    // per-thread 8 keys, statically indexed registers
    unsigned long long v[8];
#pragma unroll
    for (int j = 0; j < 8; ++j)
        v[j] = score_key(sb[tid + j * 512], tid + j * 512);

    // 8 rounds of block argmax
#pragma unroll
    for (int round = 0; round < KEV_; ++round) {
        unsigned long long m = v[0];
#pragma unroll
        for (int j = 1; j < 8; ++j) m = (v[j] > m) ? v[j] : m;
#pragma unroll
        for (int off = 16; off > 0; off >>= 1) {
            unsigned long long o = __shfl_xor_sync(0xffffffffu, m, off);
            m = (o > m) ? o : m;
        }
        if (lane == 0) wmax[warp] = m;
        __syncthreads();
        unsigned long long bm = wmax[0];
#pragma unroll
        for (int j = 1; j < 16; ++j) bm = (wmax[j] > bm) ? wmax[j] : bm;
#pragma unroll
        for (int j = 0; j < 8; ++j) if (v[j] == bm) v[j] = 0ULL;
        if (tid == 0) ev[round] = (T_ - 1) - (int)(bm & 0xFFFFFFFFu);
        __syncthreads();
    }

    // ---- parallel merge + dedup + rank (warp 0, lanes 0..23) ----
    if (warp == 0) {
        if (lane < K_) { sc[lane] = 0; sv[lane] = 0.f; }
        __syncwarp();
        // candidate value: lanes 0..7 = ev, 8..23 = uniform grid, else sentinel
        int myv;
        if (lane < KEV_)            myv = ev[lane];
        else if (lane < KEV_ + K_)  myv = (int)((float)(lane - KEV_) *
                                                ((float)(T_ - 1) / (K_ - 1)));
        else                        myv = 0x7FFFFFFF;
        // first-occurrence flag (earliest lane wins among equal values)
        int firstocc = (lane < KEV_ + K_) ? 1 : 0;
#pragma unroll
        for (int j = 0; j < KEV_ + K_; ++j) {
            int vj = __shfl_sync(0xffffffffu, myv, j);
            if (j < lane && vj == myv) firstocc = 0;
        }
        unsigned fmask = __ballot_sync(0xffffffffu, firstocc);
        // rank = number of distinct values smaller than mine
        int rank = 0;
#pragma unroll
        for (int j = 0; j < KEV_ + K_; ++j) {
            int vj = __shfl_sync(0xffffffffu, myv, j);
            if (((fmask >> j) & 1u) && vj < myv) ++rank;
        }
        const int n = __popc(fmask);
        const int nv = n < K_ ? n : K_;
        if (firstocc && rank < K_) {
            sc[rank] = myv;
            sv[rank] = (rank < nv) ? 1.f : 0.f;
        }
        __syncwarp();
        if (lane < K_) {
            g_chosen[b * K_ + lane] = sc[lane];
            g_valid[b * K_ + lane]  = (int)sv[lane];
            if (out_size >= OUT_TOTAL) {
                out[OFF_VALID + b * K_ + lane] = sv[lane];
                out[OFF_TIMES + b * K_ + lane] = (float)sc[lane] * sv[lane];
            }
        }
    }
    __syncthreads();

    // ---- warp-per-row: gather + softmax + split planes + holder ----
    {
        const int rr = warp;               // 16 warps = 16 rows
        const int row = b * K_ + rr;
        const int idx = sc[rr];
        const float vf = sv[rr];

        const float4 hv =
            ((const float4*)(hl + ((long)b * T_ + idx) * E_))[lane];
        if (out_size >= OUT_TOTAL) {
            float4 ho;
            ho.x = hv.x * vf; ho.y = hv.y * vf;
            ho.z = hv.z * vf; ho.w = hv.w * vf;
            ((float4*)(out + OFF_HOLDER + (long)row * E_))[lane] = ho;
        }
        float mx = fmaxf(fmaxf(hv.x, hv.y), fmaxf(hv.z, hv.w));
#pragma unroll
        for (int off = 16; off > 0; off >>= 1)
            mx = fmaxf(mx, __shfl_xor_sync(0xffffffffu, mx, off));
        float4 ex;
        ex.x = expf(hv.x - mx); ex.y = expf(hv.y - mx);
        ex.z = expf(hv.z - mx); ex.w = expf(hv.w - mx);
        float s = ex.x + ex.y + ex.z + ex.w;
#pragma unroll
        for (int off = 16; off > 0; off >>= 1)
            s += __shfl_xor_sync(0xffffffffu, s, off);
        float inv = 1.0f / s;
        float4 p;
        p.x = ex.x * inv; p.y = ex.y * inv; p.z = ex.z * inv; p.w = ex.w * inv;

        __nv_bfloat16* hi = g_Ahi + (long)row * DK_;
        __nv_bfloat16* lo = g_Alo + (long)row * DK_;
        uint2 h2, l2;
        split4(p, h2, l2);
        *(uint2*)(hi + D_ + lane * 4) = h2;
        *(uint2*)(lo + D_ + lane * 4) = l2;

        const float4* src = (const float4*)(state + ((long)b * T_ + idx) * D_);
#pragma unroll
        for (int t = 0; t < 8; ++t) {
            int q = lane + t * 32;
            split4(src[q], h2, l2);
            *(uint2*)(hi + q * 4) = h2;
            *(uint2*)(lo + q * 4) = l2;
        }
    }
}

// ---------------------------------------------------------------------------
// Kernel 2: HMMA split-bf16 GEMM, ldmatrix + 4-stage cp.async pipeline.
// (unchanged from R4/R5)
// ---------------------------------------------------------------------------
#define GBM 64
#define GBN 64
#define GBK 32
#define NSTAGE (DK_ / GBK)    // 36
#define STAGES 4
#define PADK 40               // k stride (bf16) per smem row; 80B, conflict-free
#define PLANE_ELEMS (64 * PADK)           // 2560 elems = 5120 B
#define STAGE_ELEMS (4 * PLANE_ELEMS)     // 4 planes
#define SMEM_BYTES (STAGES * STAGE_ELEMS * 2)   // 81920

__global__ __launch_bounds__(256)
void gemm_hmma_kernel(const float* __restrict__ bias,
                      const float* __restrict__ time_table,
                      float* __restrict__ out) {
    extern __shared__ __nv_bfloat16 smem[];   // [STAGES][4][PLANE_ELEMS]
    const uint32_t sbase = (uint32_t)__cvta_generic_to_shared(smem);

    const int tid = threadIdx.x;
    const int lane = tid & 31;
    const int warp = tid >> 5;             // 0..7
    const int warp_m = (warp & 1) * 32;    // 0 or 32
    const int warp_n = (warp >> 1) * 16;   // 0,16,32,48
    const int bm = blockIdx.y * GBM;
    const int bn = blockIdx.x * GBN;

    const int lrow = tid >> 2;
    const int lcq  = tid & 3;

    auto load_stage = [&](int st, int buf) {
        const long k0 = (long)st * GBK;
        const long aoff = (long)(bm + lrow) * DK_ + k0 + lcq * 8;
        const long boff = (long)(bn + lrow) * DK_ + k0 + lcq * 8;
        const uint32_t soff = (uint32_t)(lrow * PADK + lcq * 8);
        const uint32_t sb0 = sbase + (uint32_t)(buf * STAGE_ELEMS) * 2;
        cp16(sb0 + (0 * PLANE_ELEMS + soff) * 2, g_Ahi + aoff);
        cp16(sb0 + (1 * PLANE_ELEMS + soff) * 2, g_Alo + aoff);
        cp16(sb0 + (2 * PLANE_ELEMS + soff) * 2, g_Whi + boff);
        cp16(sb0 + (3 * PLANE_ELEMS + soff) * 2, g_Wlo + boff);
        CP_COMMIT();
    };

    const int r8 = lane & 7;
    const int quad = lane >> 3;
    const int lm = (quad & 1) * 8 + r8;
    const int lk = (quad >> 1) * 8;

    float acc[2][2][4];
#pragma unroll
    for (int i = 0; i < 2; ++i)
#pragma unroll
        for (int j = 0; j < 2; ++j)
#pragma unroll
            for (int q = 0; q < 4; ++q) acc[i][j][q] = 0.f;

    load_stage(0, 0);
    load_stage(1, 1);
    load_stage(2, 2);

    for (int st = 0; st < NSTAGE; ++st) {
        if (st < NSTAGE - 2)       { CP_WAIT(2); }
        else if (st == NSTAGE - 2) { CP_WAIT(1); }
        else                       { CP_WAIT(0); }
        __syncthreads();
        if (st + 3 < NSTAGE) load_stage(st + 3, (st + 3) & 3);

        const uint32_t sb0 = sbase + (uint32_t)((st & 3) * STAGE_ELEMS) * 2;
#pragma unroll
        for (int ks = 0; ks < 2; ++ks) {
            const int kb = ks * 16;
            uint32_t ahi[2][4], alo[2][4], bh[4], bl[4];
#pragma unroll
            for (int mt = 0; mt < 2; ++mt) {
                uint32_t ra = (uint32_t)((warp_m + mt * 16 + lm) * PADK + kb + lk) * 2;
                ldmx4(ahi[mt], sb0 + (0 * PLANE_ELEMS) * 2 + ra);
                ldmx4(alo[mt], sb0 + (1 * PLANE_ELEMS) * 2 + ra);
            }
            {
                uint32_t rb = (uint32_t)((warp_n + lm) * PADK + kb + lk) * 2;
                ldmx4(bh, sb0 + (2 * PLANE_ELEMS) * 2 + rb);
                ldmx4(bl, sb0 + (3 * PLANE_ELEMS) * 2 + rb);
            }
            uint32_t bhi0[2] = {bh[0], bh[2]}, bhi1[2] = {bh[1], bh[3]};
            uint32_t blo0[2] = {bl[0], bl[2]}, blo1[2] = {bl[1], bl[3]};

            mma_bf16(acc[0][0], ahi[0], bhi0);
            mma_bf16(acc[0][1], ahi[0], bhi1);
            mma_bf16(acc[1][0], ahi[1], bhi0);
            mma_bf16(acc[1][1], ahi[1], bhi1);
            mma_bf16(acc[0][0], ahi[0], blo0);
            mma_bf16(acc[0][1], ahi[0], blo1);
            mma_bf16(acc[1][0], ahi[1], blo0);
            mma_bf16(acc[1][1], ahi[1], blo1);
            mma_bf16(acc[0][0], alo[0], bhi0);
            mma_bf16(acc[0][1], alo[0], bhi1);
            mma_bf16(acc[1][0], alo[1], bhi0);
            mma_bf16(acc[1][1], alo[1], bhi1);
        }
    }

    // ---- epilogue ----
    const int r = lane >> 2;
    const int kq = (lane & 3) * 2;
#pragma unroll
    for (int mt = 0; mt < 2; ++mt) {
#pragma unroll
        for (int half = 0; half < 2; ++half) {
            const int m = bm + warp_m + mt * 16 + r + half * 8;
            int tt = g_chosen[m];
            tt = tt < 0 ? 0 : (tt > 511 ? 511 : tt);
            const float vf = (float)g_valid[m];
            const float* te = time_table + (long)tt * D_;
            float* op = out + OFF_ENTRIES + (long)m * D_;
#pragma unroll
            for (int nt = 0; nt < 2; ++nt) {
                const int n0 = bn + warp_n + nt * 8 + kq;
                const float c0 = acc[mt][nt][half * 2 + 0];
                const float c1 = acc[mt][nt][half * 2 + 1];
                float2 o;
                o.x = (c0 + bias[n0]     + te[n0])     * vf;
                o.y = (c1 + bias[n0 + 1] + te[n0 + 1]) * vf;
                *(float2*)(op + n0) = o;
            }
        }
    }
}

// ---------------------------------------------------------------------------
// Launch. Inputs: state_seq, holder_logits, event_scores, W, b, time_table
// ---------------------------------------------------------------------------
extern "C" void kernel_launch(void* const* d_in, const int* in_sizes, int n_in,
                              void* d_out, int out_size) {
    const float* state  = (const float*)d_in[0];
    const float* hl     = (const float*)d_in[1];
    const float* scores = (const float*)d_in[2];
    const float* W      = (const float*)d_in[3];
    const float* bias   = (const float*)d_in[4];
    const float* ttab   = (const float*)d_in[5];
    float* out = (float*)d_out;

    cudaFuncSetAttribute(gemm_hmma_kernel,
                         cudaFuncAttributeMaxDynamicSharedMemorySize,
                         SMEM_BYTES);

    prep_kernel<<<PREP_GRID, 512>>>(scores, state, hl, W, out, out_size);
    dim3 grid(D_ / GBN, M_ / GBM);   // (16, 8) = 128 CTAs
    gemm_hmma_kernel<<<grid, 256, SMEM_BYTES>>>(bias, ttab, out);
}

// round 7
// speedup vs baseline: 1.4568x; 1.1312x over previous
#include <cuda_runtime.h>
#include <cuda_bf16.h>
#include <math.h>
#include <cstdint>

// Problem constants
#define B_  32
#define T_  4096
#define D_  1024
#define E_  128
#define K_  16
#define KEV_ 8
#define DK_ (D_ + E_)          // 1152
#define M_  (B_ * K_)          // 512 rows

// Output section offsets (float32, reference return order)
#define OFF_ENTRIES 0
#define OFF_VALID   (B_ * K_ * D_)                 // 524288
#define OFF_TIMES   (OFF_VALID + B_ * K_)          // 524800
#define OFF_HOLDER  (OFF_TIMES + B_ * K_)          // 525312
#define OUT_TOTAL   (OFF_HOLDER + B_ * K_ * E_)    // 590848

// Scratch: split-bf16 planes for A (gathered raw) and B (W)
__device__ int            g_chosen[M_];
__device__ int            g_valid[M_];
__device__ __nv_bfloat16  g_Ahi[(long)M_ * DK_];
__device__ __nv_bfloat16  g_Alo[(long)M_ * DK_];
__device__ __nv_bfloat16  g_Whi[(long)D_ * DK_];
__device__ __nv_bfloat16  g_Wlo[(long)D_ * DK_];

// ---------------------------------------------------------------------------
// helpers
// ---------------------------------------------------------------------------
__device__ __forceinline__ void split4(float4 v, uint2& hi, uint2& lo) {
    __nv_bfloat16 h0 = __float2bfloat16_rn(v.x);
    __nv_bfloat16 h1 = __float2bfloat16_rn(v.y);
    __nv_bfloat16 h2 = __float2bfloat16_rn(v.z);
    __nv_bfloat16 h3 = __float2bfloat16_rn(v.w);
    __nv_bfloat16 l0 = __float2bfloat16_rn(v.x - __bfloat162float(h0));
    __nv_bfloat16 l1 = __float2bfloat16_rn(v.y - __bfloat162float(h1));
    __nv_bfloat16 l2 = __float2bfloat16_rn(v.z - __bfloat162float(h2));
    __nv_bfloat16 l3 = __float2bfloat16_rn(v.w - __bfloat162float(h3));
    __nv_bfloat162 H01, H23, L01, L23;
    H01.x = h0; H01.y = h1; H23.x = h2; H23.y = h3;
    L01.x = l0; L01.y = l1; L23.x = l2; L23.y = l3;
    hi = make_uint2(*(uint32_t*)&H01, *(uint32_t*)&H23);
    lo = make_uint2(*(uint32_t*)&L01, *(uint32_t*)&L23);
}

__device__ __forceinline__ void mma_bf16(float* c, const uint32_t* a,
                                         const uint32_t* b) {
    asm volatile(
        "mma.sync.aligned.m16n8k16.row.col.f32.bf16.bf16.f32 "
        "{%0,%1,%2,%3}, {%4,%5,%6,%7}, {%8,%9}, {%0,%1,%2,%3};"
        : "+f"(c[0]), "+f"(c[1]), "+f"(c[2]), "+f"(c[3])
        : "r"(a[0]), "r"(a[1]), "r"(a[2]), "r"(a[3]),
          "r"(b[0]), "r"(b[1]));
}

__device__ __forceinline__ void ldmx4(uint32_t* r, uint32_t addr) {
    asm volatile(
        "ldmatrix.sync.aligned.m8n8.x4.shared.b16 {%0,%1,%2,%3}, [%4];"
        : "=r"(r[0]), "=r"(r[1]), "=r"(r[2]), "=r"(r[3]) : "r"(addr));
}

__device__ __forceinline__ void cp16(uint32_t smem_dst, const void* gsrc) {
    asm volatile("cp.async.cg.shared.global [%0], [%1], 16;"
                 :: "r"(smem_dst),
                    "l"((unsigned long long)__cvta_generic_to_global(gsrc)));
}
#define CP_COMMIT() asm volatile("cp.async.commit_group;")
#define CP_WAIT(n)  asm volatile("cp.async.wait_group %0;" :: "n"(n))

__device__ __forceinline__ unsigned long long score_key(float v, int i) {
    unsigned u = __float_as_uint(v);
    u = (u & 0x80000000u) ? ~u : (u | 0x80000000u);
    return ((unsigned long long)u << 32) | (unsigned)(T_ - 1 - i);
}

// ---------------------------------------------------------------------------
// Kernel 1 (prep, heterogeneous grid): unchanged from R6.
//   blocks [0,32): choose + build; blocks [32,608): pack W.
// ---------------------------------------------------------------------------
#define PACK_BLOCKS ((D_ * DK_ / 4) / 512)   // 576
#define PREP_GRID   (B_ + PACK_BLOCKS)       // 608

__global__ __launch_bounds__(512)
void prep_kernel(const float* __restrict__ scores,
                 const float* __restrict__ state,
                 const float* __restrict__ hl,
                 const float* __restrict__ W,
                 float* __restrict__ out, int out_size) {
    if (blockIdx.x >= B_) {
        long i = (long)(blockIdx.x - B_) * 512 + threadIdx.x;  // float4 idx
        float4 v = ((const float4*)W)[i];
        uint2 hi, lo;
        split4(v, hi, lo);
        *(uint2*)(g_Whi + i * 4) = hi;
        *(uint2*)(g_Wlo + i * 4) = lo;
        return;
    }

    __shared__ unsigned long long wmax[16];
    __shared__ int ev[KEV_];
    __shared__ int   sc[K_];
    __shared__ float sv[K_];

    const int b = blockIdx.x;
    const int tid = threadIdx.x;
    const int lane = tid & 31, warp = tid >> 5;
    const float* sb = scores + (long)b * T_;

    unsigned long long v[8];
#pragma unroll
    for (int j = 0; j < 8; ++j)
        v[j] = score_key(sb[tid + j * 512], tid + j * 512);

#pragma unroll
    for (int round = 0; round < KEV_; ++round) {
        unsigned long long m = v[0];
#pragma unroll
        for (int j = 1; j < 8; ++j) m = (v[j] > m) ? v[j] : m;
#pragma unroll
        for (int off = 16; off > 0; off >>= 1) {
            unsigned long long o = __shfl_xor_sync(0xffffffffu, m, off);
            m = (o > m) ? o : m;
        }
        if (lane == 0) wmax[warp] = m;
        __syncthreads();
        unsigned long long bm = wmax[0];
#pragma unroll
        for (int j = 1; j < 16; ++j) bm = (wmax[j] > bm) ? wmax[j] : bm;
#pragma unroll
        for (int j = 0; j < 8; ++j) if (v[j] == bm) v[j] = 0ULL;
        if (tid == 0) ev[round] = (T_ - 1) - (int)(bm & 0xFFFFFFFFu);
        __syncthreads();
    }

    if (warp == 0) {
        if (lane < K_) { sc[lane] = 0; sv[lane] = 0.f; }
        __syncwarp();
        int myv;
        if (lane < KEV_)            myv = ev[lane];
        else if (lane < KEV_ + K_)  myv = (int)((float)(lane - KEV_) *
                                                ((float)(T_ - 1) / (K_ - 1)));
        else                        myv = 0x7FFFFFFF;
        int firstocc = (lane < KEV_ + K_) ? 1 : 0;
#pragma unroll
        for (int j = 0; j < KEV_ + K_; ++j) {
            int vj = __shfl_sync(0xffffffffu, myv, j);
            if (j < lane && vj == myv) firstocc = 0;
        }
        unsigned fmask = __ballot_sync(0xffffffffu, firstocc);
        int rank = 0;
#pragma unroll
        for (int j = 0; j < KEV_ + K_; ++j) {
            int vj = __shfl_sync(0xffffffffu, myv, j);
            if (((fmask >> j) & 1u) && vj < myv) ++rank;
        }
        const int n = __popc(fmask);
        const int nv = n < K_ ? n : K_;
        if (firstocc && rank < K_) {
            sc[rank] = myv;
            sv[rank] = (rank < nv) ? 1.f : 0.f;
        }
        __syncwarp();
        if (lane < K_) {
            g_chosen[b * K_ + lane] = sc[lane];
            g_valid[b * K_ + lane]  = (int)sv[lane];
            if (out_size >= OUT_TOTAL) {
                out[OFF_VALID + b * K_ + lane] = sv[lane];
                out[OFF_TIMES + b * K_ + lane] = (float)sc[lane] * sv[lane];
            }
        }
    }
    __syncthreads();

    {
        const int rr = warp;
        const int row = b * K_ + rr;
        const int idx = sc[rr];
        const float vf = sv[rr];

        const float4 hv =
            ((const float4*)(hl + ((long)b * T_ + idx) * E_))[lane];
        if (out_size >= OUT_TOTAL) {
            float4 ho;
            ho.x = hv.x * vf; ho.y = hv.y * vf;
            ho.z = hv.z * vf; ho.w = hv.w * vf;
            ((float4*)(out + OFF_HOLDER + (long)row * E_))[lane] = ho;
        }
        float mx = fmaxf(fmaxf(hv.x, hv.y), fmaxf(hv.z, hv.w));
#pragma unroll
        for (int off = 16; off > 0; off >>= 1)
            mx = fmaxf(mx, __shfl_xor_sync(0xffffffffu, mx, off));
        float4 ex;
        ex.x = expf(hv.x - mx); ex.y = expf(hv.y - mx);
        ex.z = expf(hv.z - mx); ex.w = expf(hv.w - mx);
        float s = ex.x + ex.y + ex.z + ex.w;
#pragma unroll
        for (int off = 16; off > 0; off >>= 1)
            s += __shfl_xor_sync(0xffffffffu, s, off);
        float inv = 1.0f / s;
        float4 p;
        p.x = ex.x * inv; p.y = ex.y * inv; p.z = ex.z * inv; p.w = ex.w * inv;

        __nv_bfloat16* hi = g_Ahi + (long)row * DK_;
        __nv_bfloat16* lo = g_Alo + (long)row * DK_;
        uint2 h2, l2;
        split4(p, h2, l2);
        *(uint2*)(hi + D_ + lane * 4) = h2;
        *(uint2*)(lo + D_ + lane * 4) = l2;

        const float4* src = (const float4*)(state + ((long)b * T_ + idx) * D_);
#pragma unroll
        for (int t = 0; t < 8; ++t) {
            int q = lane + t * 32;
            split4(src[q], h2, l2);
            *(uint2*)(hi + q * 4) = h2;
            *(uint2*)(lo + q * 4) = l2;
        }
    }
}

// ---------------------------------------------------------------------------
// Kernel 2: HMMA split-bf16 GEMM, 512 threads, 16 warps (4x4), warp tile
// 16x16, GBK=64, 3-stage cp.async pipeline. 2 acc chains/warp, 8 chains/SMSP.
// ---------------------------------------------------------------------------
#define GBM 64
#define GBN 64
#define GBK 64
#define NSTAGE (DK_ / GBK)    // 18
#define STAGES 3
#define PADK 72               // k stride (bf16) per smem row; 144B, conflict-free
#define PLANE_ELEMS (64 * PADK)           // 4608 elems = 9216 B
#define STAGE_ELEMS (4 * PLANE_ELEMS)     // 4 planes (Ahi,Alo,Bhi,Blo)
#define SMEM_BYTES (STAGES * STAGE_ELEMS * 2)   // 110592

__global__ __launch_bounds__(512)
void gemm_hmma_kernel(const float* __restrict__ bias,
                      const float* __restrict__ time_table,
                      float* __restrict__ out) {
    extern __shared__ __nv_bfloat16 smem[];   // [STAGES][4][PLANE_ELEMS]
    const uint32_t sbase = (uint32_t)__cvta_generic_to_shared(smem);

    const int tid = threadIdx.x;
    const int lane = tid & 31;
    const int warp = tid >> 5;              // 0..15
    const int warp_m = (warp & 3) * 16;     // 0,16,32,48
    const int warp_n = (warp >> 2) * 16;    // 0,16,32,48
    const int bm = blockIdx.y * GBM;
    const int bn = blockIdx.x * GBN;

    // cp.async mapping: 512 threads cover one 64x64 bf16 plane per pass
    const int lrow = tid >> 3;              // 0..63
    const int lcq  = tid & 7;               // 8 x 16B chunks per 128B row

    auto load_stage = [&](int st, int buf) {
        const long k0 = (long)st * GBK;
        const long aoff = (long)(bm + lrow) * DK_ + k0 + lcq * 8;
        const long boff = (long)(bn + lrow) * DK_ + k0 + lcq * 8;
        const uint32_t soff = (uint32_t)(lrow * PADK + lcq * 8);
        const uint32_t sb0 = sbase + (uint32_t)(buf * STAGE_ELEMS) * 2;
        cp16(sb0 + (0 * PLANE_ELEMS + soff) * 2, g_Ahi + aoff);
        cp16(sb0 + (1 * PLANE_ELEMS + soff) * 2, g_Alo + aoff);
        cp16(sb0 + (2 * PLANE_ELEMS + soff) * 2, g_Whi + boff);
        cp16(sb0 + (3 * PLANE_ELEMS + soff) * 2, g_Wlo + boff);
        CP_COMMIT();
    };

    // ldmatrix lane mapping
    const int r8 = lane & 7;
    const int quad = lane >> 3;
    const int lm = (quad & 1) * 8 + r8;     // row within 16
    const int lk = (quad >> 1) * 8;         // k offset within 16

    float acc[2][4];
#pragma unroll
    for (int j = 0; j < 2; ++j)
#pragma unroll
        for (int q = 0; q < 4; ++q) acc[j][q] = 0.f;

    load_stage(0, 0);
    load_stage(1, 1);

    for (int st = 0; st < NSTAGE; ++st) {
        if (st + 1 < NSTAGE) { CP_WAIT(1); } else { CP_WAIT(0); }
        __syncthreads();
        if (st + 2 < NSTAGE) load_stage(st + 2, (st + 2) % 3);

        const uint32_t sb0 = sbase + (uint32_t)((st % 3) * STAGE_ELEMS) * 2;
        const uint32_t abase = sb0 + 0;                        // Ahi
        const uint32_t lbase = sb0 + (1 * PLANE_ELEMS) * 2;    // Alo
        const uint32_t bbase = sb0 + (2 * PLANE_ELEMS) * 2;    // Bhi
        const uint32_t mbase = sb0 + (3 * PLANE_ELEMS) * 2;    // Blo

#pragma unroll
        for (int ks = 0; ks < 4; ++ks) {
            const int kb = ks * 16;
            uint32_t ah[4], al[4], bh[4], bl[4];
            const uint32_t ra = (uint32_t)((warp_m + lm) * PADK + kb + lk) * 2;
            const uint32_t rb = (uint32_t)((warp_n + lm) * PADK + kb + lk) * 2;
            ldmx4(ah, abase + ra);
            ldmx4(al, lbase + ra);
            ldmx4(bh, bbase + rb);
            ldmx4(bl, mbase + rb);

            uint32_t bh0[2] = {bh[0], bh[2]}, bh1[2] = {bh[1], bh[3]};
            uint32_t bl0[2] = {bl[0], bl[2]}, bl1[2] = {bl[1], bl[3]};

            mma_bf16(acc[0], ah, bh0);
            mma_bf16(acc[1], ah, bh1);
            mma_bf16(acc[0], ah, bl0);
            mma_bf16(acc[1], ah, bl1);
            mma_bf16(acc[0], al, bh0);
            mma_bf16(acc[1], al, bh1);
        }
    }

    // ---- epilogue: + bias + time_table[clip(chosen,0,511)], * valid ----
    const int r = lane >> 2;
    const int kq = (lane & 3) * 2;
#pragma unroll
    for (int half = 0; half < 2; ++half) {
        const int m = bm + warp_m + r + half * 8;
        int tt = g_chosen[m];
        tt = tt < 0 ? 0 : (tt > 511 ? 511 : tt);
        const float vf = (float)g_valid[m];
        const float* te = time_table + (long)tt * D_;
        float* op = out + OFF_ENTRIES + (long)m * D_;
#pragma unroll
        for (int nt = 0; nt < 2; ++nt) {
            const int n0 = bn + warp_n + nt * 8 + kq;
            const float c0 = acc[nt][half * 2 + 0];
            const float c1 = acc[nt][half * 2 + 1];
            float2 o;
            o.x = (c0 + bias[n0]     + te[n0])     * vf;
            o.y = (c1 + bias[n0 + 1] + te[n0 + 1]) * vf;
            *(float2*)(op + n0) = o;
        }
    }
}

// ---------------------------------------------------------------------------
// Launch. Inputs: state_seq, holder_logits, event_scores, W, b, time_table
// ---------------------------------------------------------------------------
extern "C" void kernel_launch(void* const* d_in, const int* in_sizes, int n_in,
                              void* d_out, int out_size) {
    const float* state  = (const float*)d_in[0];
    const float* hl     = (const float*)d_in[1];
    const float* scores = (const float*)d_in[2];
    const float* W      = (const float*)d_in[3];
    const float* bias   = (const float*)d_in[4];
    const float* ttab   = (const float*)d_in[5];
    float* out = (float*)d_out;

    cudaFuncSetAttribute(gemm_hmma_kernel,
                         cudaFuncAttributeMaxDynamicSharedMemorySize,
                         SMEM_BYTES);

    prep_kernel<<<PREP_GRID, 512>>>(scores, state, hl, W, out, out_size);
    dim3 grid(D_ / GBN, M_ / GBM);   // (16, 8) = 128 CTAs
    gemm_hmma_kernel<<<grid, 512, SMEM_BYTES>>>(bias, ttab, out);
}

// round 8
// speedup vs baseline: 1.4687x; 1.0082x over previous
#include <cuda_runtime.h>
#include <cuda_bf16.h>
#include <math.h>
#include <cstdint>

// Problem constants
#define B_  32
#define T_  4096
#define D_  1024
#define E_  128
#define K_  16
#define KEV_ 8
#define DK_ (D_ + E_)          // 1152
#define M_  (B_ * K_)          // 512 rows

// Output section offsets (float32, reference return order)
#define OFF_ENTRIES 0
#define OFF_VALID   (B_ * K_ * D_)                 // 524288
#define OFF_TIMES   (OFF_VALID + B_ * K_)          // 524800
#define OFF_HOLDER  (OFF_TIMES + B_ * K_)          // 525312
#define OUT_TOTAL   (OFF_HOLDER + B_ * K_ * E_)    // 590848

// Scratch: split-bf16 planes for A (gathered raw) and B (W)
__device__ int            g_chosen[M_];
__device__ int            g_valid[M_];
__device__ __nv_bfloat16  g_Ahi[(long)M_ * DK_];
__device__ __nv_bfloat16  g_Alo[(long)M_ * DK_];
__device__ __nv_bfloat16  g_Whi[(long)D_ * DK_];
__device__ __nv_bfloat16  g_Wlo[(long)D_ * DK_];

// ---------------------------------------------------------------------------
// helpers
// ---------------------------------------------------------------------------
__device__ __forceinline__ void split4(float4 v, uint2& hi, uint2& lo) {
    __nv_bfloat16 h0 = __float2bfloat16_rn(v.x);
    __nv_bfloat16 h1 = __float2bfloat16_rn(v.y);
    __nv_bfloat16 h2 = __float2bfloat16_rn(v.z);
    __nv_bfloat16 h3 = __float2bfloat16_rn(v.w);
    __nv_bfloat16 l0 = __float2bfloat16_rn(v.x - __bfloat162float(h0));
    __nv_bfloat16 l1 = __float2bfloat16_rn(v.y - __bfloat162float(h1));
    __nv_bfloat16 l2 = __float2bfloat16_rn(v.z - __bfloat162float(h2));
    __nv_bfloat16 l3 = __float2bfloat16_rn(v.w - __bfloat162float(h3));
    __nv_bfloat162 H01, H23, L01, L23;
    H01.x = h0; H01.y = h1; H23.x = h2; H23.y = h3;
    L01.x = l0; L01.y = l1; L23.x = l2; L23.y = l3;
    hi = make_uint2(*(uint32_t*)&H01, *(uint32_t*)&H23);
    lo = make_uint2(*(uint32_t*)&L01, *(uint32_t*)&L23);
}

__device__ __forceinline__ void mma_bf16(float* c, const uint32_t* a,
                                         const uint32_t* b) {
    asm volatile(
        "mma.sync.aligned.m16n8k16.row.col.f32.bf16.bf16.f32 "
        "{%0,%1,%2,%3}, {%4,%5,%6,%7}, {%8,%9}, {%0,%1,%2,%3};"
        : "+f"(c[0]), "+f"(c[1]), "+f"(c[2]), "+f"(c[3])
        : "r"(a[0]), "r"(a[1]), "r"(a[2]), "r"(a[3]),
          "r"(b[0]), "r"(b[1]));
}

__device__ __forceinline__ void ldmx4(uint32_t* r, uint32_t addr) {
    asm volatile(
        "ldmatrix.sync.aligned.m8n8.x4.shared.b16 {%0,%1,%2,%3}, [%4];"
        : "=r"(r[0]), "=r"(r[1]), "=r"(r[2]), "=r"(r[3]) : "r"(addr));
}

__device__ __forceinline__ void cp16(uint32_t smem_dst, const void* gsrc) {
    asm volatile("cp.async.cg.shared.global [%0], [%1], 16;"
                 :: "r"(smem_dst),
                    "l"((unsigned long long)__cvta_generic_to_global(gsrc)));
}
#define CP_COMMIT() asm volatile("cp.async.commit_group;")
#define CP_WAIT(n)  asm volatile("cp.async.wait_group %0;" :: "n"(n))

__device__ __forceinline__ unsigned long long score_key(float v, int i) {
    unsigned u = __float_as_uint(v);
    u = (u & 0x80000000u) ? ~u : (u | 0x80000000u);
    return ((unsigned long long)u << 32) | (unsigned)(T_ - 1 - i);
}

// ---------------------------------------------------------------------------
// Kernel 1 (prep, heterogeneous grid): unchanged from R6/R7.
//   blocks [0,32): choose + build; blocks [32,608): pack W.
// ---------------------------------------------------------------------------
#define PACK_BLOCKS ((D_ * DK_ / 4) / 512)   // 576
#define PREP_GRID   (B_ + PACK_BLOCKS)       // 608

__global__ __launch_bounds__(512)
void prep_kernel(const float* __restrict__ scores,
                 const float* __restrict__ state,
                 const float* __restrict__ hl,
                 const float* __restrict__ W,
                 float* __restrict__ out, int out_size) {
    if (blockIdx.x >= B_) {
        long i = (long)(blockIdx.x - B_) * 512 + threadIdx.x;  // float4 idx
        float4 v = ((const float4*)W)[i];
        uint2 hi, lo;
        split4(v, hi, lo);
        *(uint2*)(g_Whi + i * 4) = hi;
        *(uint2*)(g_Wlo + i * 4) = lo;
        return;
    }

    __shared__ unsigned long long wmax[16];
    __shared__ int ev[KEV_];
    __shared__ int   sc[K_];
    __shared__ float sv[K_];

    const int b = blockIdx.x;
    const int tid = threadIdx.x;
    const int lane = tid & 31, warp = tid >> 5;
    const float* sb = scores + (long)b * T_;

    unsigned long long v[8];
#pragma unroll
    for (int j = 0; j < 8; ++j)
        v[j] = score_key(sb[tid + j * 512], tid + j * 512);

#pragma unroll
    for (int round = 0; round < KEV_; ++round) {
        unsigned long long m = v[0];
#pragma unroll
        for (int j = 1; j < 8; ++j) m = (v[j] > m) ? v[j] : m;
#pragma unroll
        for (int off = 16; off > 0; off >>= 1) {
            unsigned long long o = __shfl_xor_sync(0xffffffffu, m, off);
            m = (o > m) ? o : m;
        }
        if (lane == 0) wmax[warp] = m;
        __syncthreads();
        unsigned long long bm = wmax[0];
#pragma unroll
        for (int j = 1; j < 16; ++j) bm = (wmax[j] > bm) ? wmax[j] : bm;
#pragma unroll
        for (int j = 0; j < 8; ++j) if (v[j] == bm) v[j] = 0ULL;
        if (tid == 0) ev[round] = (T_ - 1) - (int)(bm & 0xFFFFFFFFu);
        __syncthreads();
    }

    if (warp == 0) {
        if (lane < K_) { sc[lane] = 0; sv[lane] = 0.f; }
        __syncwarp();
        int myv;
        if (lane < KEV_)            myv = ev[lane];
        else if (lane < KEV_ + K_)  myv = (int)((float)(lane - KEV_) *
                                                ((float)(T_ - 1) / (K_ - 1)));
        else                        myv = 0x7FFFFFFF;
        int firstocc = (lane < KEV_ + K_) ? 1 : 0;
#pragma unroll
        for (int j = 0; j < KEV_ + K_; ++j) {
            int vj = __shfl_sync(0xffffffffu, myv, j);
            if (j < lane && vj == myv) firstocc = 0;
        }
        unsigned fmask = __ballot_sync(0xffffffffu, firstocc);
        int rank = 0;
#pragma unroll
        for (int j = 0; j < KEV_ + K_; ++j) {
            int vj = __shfl_sync(0xffffffffu, myv, j);
            if (((fmask >> j) & 1u) && vj < myv) ++rank;
        }
        const int n = __popc(fmask);
        const int nv = n < K_ ? n : K_;
        if (firstocc && rank < K_) {
            sc[rank] = myv;
            sv[rank] = (rank < nv) ? 1.f : 0.f;
        }
        __syncwarp();
        if (lane < K_) {
            g_chosen[b * K_ + lane] = sc[lane];
            g_valid[b * K_ + lane]  = (int)sv[lane];
            if (out_size >= OUT_TOTAL) {
                out[OFF_VALID + b * K_ + lane] = sv[lane];
                out[OFF_TIMES + b * K_ + lane] = (float)sc[lane] * sv[lane];
            }
        }
    }
    __syncthreads();

    {
        const int rr = warp;
        const int row = b * K_ + rr;
        const int idx = sc[rr];
        const float vf = sv[rr];

        const float4 hv =
            ((const float4*)(hl + ((long)b * T_ + idx) * E_))[lane];
        if (out_size >= OUT_TOTAL) {
            float4 ho;
            ho.x = hv.x * vf; ho.y = hv.y * vf;
            ho.z = hv.z * vf; ho.w = hv.w * vf;
            ((float4*)(out + OFF_HOLDER + (long)row * E_))[lane] = ho;
        }
        float mx = fmaxf(fmaxf(hv.x, hv.y), fmaxf(hv.z, hv.w));
#pragma unroll
        for (int off = 16; off > 0; off >>= 1)
            mx = fmaxf(mx, __shfl_xor_sync(0xffffffffu, mx, off));
        float4 ex;
        ex.x = expf(hv.x - mx); ex.y = expf(hv.y - mx);
        ex.z = expf(hv.z - mx); ex.w = expf(hv.w - mx);
        float s = ex.x + ex.y + ex.z + ex.w;
#pragma unroll
        for (int off = 16; off > 0; off >>= 1)
            s += __shfl_xor_sync(0xffffffffu, s, off);
        float inv = 1.0f / s;
        float4 p;
        p.x = ex.x * inv; p.y = ex.y * inv; p.z = ex.z * inv; p.w = ex.w * inv;

        __nv_bfloat16* hi = g_Ahi + (long)row * DK_;
        __nv_bfloat16* lo = g_Alo + (long)row * DK_;
        uint2 h2, l2;
        split4(p, h2, l2);
        *(uint2*)(hi + D_ + lane * 4) = h2;
        *(uint2*)(lo + D_ + lane * 4) = l2;

        const float4* src = (const float4*)(state + ((long)b * T_ + idx) * D_);
#pragma unroll
        for (int t = 0; t < 8; ++t) {
            int q = lane + t * 32;
            split4(src[q], h2, l2);
            *(uint2*)(hi + q * 4) = h2;
            *(uint2*)(lo + q * 4) = l2;
        }
    }
}

// ---------------------------------------------------------------------------
// Kernel 2: HMMA split-bf16 GEMM with intra-CTA split-k.
// 512 threads = 16 warps as 2(m) x 4(n) x 2(k-split); warp tile 32x16.
// Each warp handles half of each k64 chunk -> 4 acc chains, 6 ldmx4 : 12 MMA.
// Final cross-k reduction through padded smem.
// ---------------------------------------------------------------------------
#define GBM 64
#define GBN 64
#define GBK 64
#define NSTAGE (DK_ / GBK)    // 18
#define STAGES 3
#define PADK 72               // k stride (bf16) per smem row; 144B, conflict-free
#define PLANE_ELEMS (64 * PADK)           // 4608 elems = 9216 B
#define STAGE_ELEMS (4 * PLANE_ELEMS)     // 4 planes (Ahi,Alo,Bhi,Blo)
#define SMEM_BYTES (STAGES * STAGE_ELEMS * 2)   // 110592 (>= 17408 reduction buf)

__global__ __launch_bounds__(512)
void gemm_hmma_kernel(const float* __restrict__ bias,
                      const float* __restrict__ time_table,
                      float* __restrict__ out) {
    extern __shared__ __nv_bfloat16 smem[];   // [STAGES][4][PLANE_ELEMS]
    const uint32_t sbase = (uint32_t)__cvta_generic_to_shared(smem);

    const int tid = threadIdx.x;
    const int lane = tid & 31;
    const int warp = tid >> 5;                 // 0..15
    const int ksplit = warp & 1;               // 0 or 1
    const int wgroup = warp >> 1;              // 0..7 (shared by k partners)
    const int warp_m = ((warp >> 1) & 1) * 32; // 0 or 32
    const int warp_n = (warp >> 2) * 16;       // 0,16,32,48
    const int bm = blockIdx.y * GBM;
    const int bn = blockIdx.x * GBN;

    // cp.async mapping: 512 threads cover one 64x64 bf16 plane per pass
    const int lrow = tid >> 3;              // 0..63
    const int lcq  = tid & 7;               // 8 x 16B chunks per 128B row

    auto load_stage = [&](int st, int buf) {
        const long k0 = (long)st * GBK;
        const long aoff = (long)(bm + lrow) * DK_ + k0 + lcq * 8;
        const long boff = (long)(bn + lrow) * DK_ + k0 + lcq * 8;
        const uint32_t soff = (uint32_t)(lrow * PADK + lcq * 8);
        const uint32_t sb0 = sbase + (uint32_t)(buf * STAGE_ELEMS) * 2;
        cp16(sb0 + (0 * PLANE_ELEMS + soff) * 2, g_Ahi + aoff);
        cp16(sb0 + (1 * PLANE_ELEMS + soff) * 2, g_Alo + aoff);
        cp16(sb0 + (2 * PLANE_ELEMS + soff) * 2, g_Whi + boff);
        cp16(sb0 + (3 * PLANE_ELEMS + soff) * 2, g_Wlo + boff);
        CP_COMMIT();
    };

    // ldmatrix lane mapping
    const int r8 = lane & 7;
    const int quad = lane >> 3;
    const int lm = (quad & 1) * 8 + r8;     // row within 16
    const int lk = (quad >> 1) * 8;         // k offset within 16

    float acc[2][2][4];
#pragma unroll
    for (int i = 0; i < 2; ++i)
#pragma unroll
        for (int j = 0; j < 2; ++j)
#pragma unroll
            for (int q = 0; q < 4; ++q) acc[i][j][q] = 0.f;

    load_stage(0, 0);
    load_stage(1, 1);

    for (int st = 0; st < NSTAGE; ++st) {
        if (st + 1 < NSTAGE) { CP_WAIT(1); } else { CP_WAIT(0); }
        __syncthreads();
        if (st + 2 < NSTAGE) load_stage(st + 2, (st + 2) % 3);

        const uint32_t sb0 = sbase + (uint32_t)((st % 3) * STAGE_ELEMS) * 2;
        const uint32_t abase = sb0 + 0;                        // Ahi
        const uint32_t lbase = sb0 + (1 * PLANE_ELEMS) * 2;    // Alo
        const uint32_t bbase = sb0 + (2 * PLANE_ELEMS) * 2;    // Bhi
        const uint32_t mbase = sb0 + (3 * PLANE_ELEMS) * 2;    // Blo

#pragma unroll
        for (int kss = 0; kss < 2; ++kss) {
            const int kb = (ksplit * 2 + kss) * 16;   // this warp's k16 step
            uint32_t ah[2][4], al[2][4], bh[4], bl[4];
#pragma unroll
            for (int mt = 0; mt < 2; ++mt) {
                const uint32_t ra =
                    (uint32_t)((warp_m + mt * 16 + lm) * PADK + kb + lk) * 2;
                ldmx4(ah[mt], abase + ra);
                ldmx4(al[mt], lbase + ra);
            }
            const uint32_t rb = (uint32_t)((warp_n + lm) * PADK + kb + lk) * 2;
            ldmx4(bh, bbase + rb);
            ldmx4(bl, mbase + rb);

            uint32_t bh0[2] = {bh[0], bh[2]}, bh1[2] = {bh[1], bh[3]};
            uint32_t bl0[2] = {bl[0], bl[2]}, bl1[2] = {bl[1], bl[3]};

            // interleave across 4 chains for ILP
            mma_bf16(acc[0][0], ah[0], bh0);
            mma_bf16(acc[0][1], ah[0], bh1);
            mma_bf16(acc[1][0], ah[1], bh0);
            mma_bf16(acc[1][1], ah[1], bh1);
            mma_bf16(acc[0][0], ah[0], bl0);
            mma_bf16(acc[0][1], ah[0], bl1);
            mma_bf16(acc[1][0], ah[1], bl0);
            mma_bf16(acc[1][1], ah[1], bl1);
            mma_bf16(acc[0][0], al[0], bh0);
            mma_bf16(acc[0][1], al[0], bh1);
            mma_bf16(acc[1][0], al[1], bh0);
            mma_bf16(acc[1][1], al[1], bh1);
        }
    }

    // ---- cross-k reduction: ksplit=1 writes partials, ksplit=0 adds ----
    __syncthreads();   // all ldmatrix reads of stage smem complete
    float* red = (float*)smem;   // [8 groups][32 lanes][17] floats, padded
    float* myred = red + ((wgroup * 32) + lane) * 17;
    if (ksplit == 1) {
#pragma unroll
        for (int mt = 0; mt < 2; ++mt)
#pragma unroll
            for (int nt = 0; nt < 2; ++nt)
#pragma unroll
                for (int q = 0; q < 4; ++q)
                    myred[mt * 8 + nt * 4 + q] = acc[mt][nt][q];
    }
    __syncthreads();
    if (ksplit == 0) {
#pragma unroll
        for (int mt = 0; mt < 2; ++mt)
#pragma unroll
            for (int nt = 0; nt < 2; ++nt)
#pragma unroll
                for (int q = 0; q < 4; ++q)
                    acc[mt][nt][q] += myred[mt * 8 + nt * 4 + q];

        // ---- epilogue: + bias + time_table[clip(chosen,0,511)], * valid ----
        const int r = lane >> 2;
        const int kq = (lane & 3) * 2;
#pragma unroll
        for (int mt = 0; mt < 2; ++mt) {
#pragma unroll
            for (int half = 0; half < 2; ++half) {
                const int m = bm + warp_m + mt * 16 + r + half * 8;
                int tt = g_chosen[m];
                tt = tt < 0 ? 0 : (tt > 511 ? 511 : tt);
                const float vf = (float)g_valid[m];
                const float* te = time_table + (long)tt * D_;
                float* op = out + OFF_ENTRIES + (long)m * D_;
#pragma unroll
                for (int nt = 0; nt < 2; ++nt) {
                    const int n0 = bn + warp_n + nt * 8 + kq;
                    const float c0 = acc[mt][nt][half * 2 + 0];
                    const float c1 = acc[mt][nt][half * 2 + 1];
                    float2 o;
                    o.x = (c0 + bias[n0]     + te[n0])     * vf;
                    o.y = (c1 + bias[n0 + 1] + te[n0 + 1]) * vf;
                    *(float2*)(op + n0) = o;
                }
            }
        }
    }
}

// ---------------------------------------------------------------------------
// Launch. Inputs: state_seq, holder_logits, event_scores, W, b, time_table
// ---------------------------------------------------------------------------
extern "C" void kernel_launch(void* const* d_in, const int* in_sizes, int n_in,
                              void* d_out, int out_size) {
    const float* state  = (const float*)d_in[0];
    const float* hl     = (const float*)d_in[1];
    const float* scores = (const float*)d_in[2];
    const float* W      = (const float*)d_in[3];
    const float* bias   = (const float*)d_in[4];
    const float* ttab   = (const float*)d_in[5];
    float* out = (float*)d_out;

    cudaFuncSetAttribute(gemm_hmma_kernel,
                         cudaFuncAttributeMaxDynamicSharedMemorySize,
                         SMEM_BYTES);

    prep_kernel<<<PREP_GRID, 512>>>(scores, state, hl, W, out, out_size);
    dim3 grid(D_ / GBN, M_ / GBM);   // (16, 8) = 128 CTAs
    gemm_hmma_kernel<<<grid, 512, SMEM_BYTES>>>(bias, ttab, out);
}